// round 1
// baseline (speedup 1.0000x reference)
#include <cuda_runtime.h>
#include <cstddef>

#define HEADS  8
#define NNODES 8192
#define NEDGES 131072
#define FIN    16
#define CT1    64      // heads*8
#define CT2    1024    // heads*128
#define NEG    0.2f

// ---------------- scratch (static __device__, no allocation) ----------------
__device__ float g_h1lin[NNODES*CT1];
__device__ float g_as1[NNODES*HEADS];
__device__ float g_ad1[NNODES*HEADS];
__device__ float g_h1[NNODES*CT1];
__device__ float g_h2lin[(size_t)NNODES*CT2];   // 32MB
__device__ float g_as2[NNODES*HEADS];
__device__ float g_ad2[NNODES*HEADS];
__device__ float g_h2[(size_t)NNODES*CT2];      // 32MB
__device__ int   g_deg[NNODES];
__device__ int   g_rowptr[NNODES+1];
__device__ int   g_cursor[NNODES];
__device__ int   g_srcs[NEDGES];
__device__ int   g_is64;
__device__ float g_advp[512*128];
__device__ float g_valp[512*512];

__device__ __forceinline__ float lrelu(float x){ return x > 0.f ? x : NEG*x; }

// ---------------- edge dtype sniff (int64 vs int32) ----------------
__global__ void detect_kernel(const int* e32){
    __shared__ int nz;
    if (threadIdx.x == 0) nz = 0;
    __syncthreads();
    int v = 0;
    for (int i = threadIdx.x; i < 8192; i += 256) v |= e32[2*i+1];
    if (v) atomicOr(&nz, 1);
    __syncthreads();
    if (threadIdx.x == 0) g_is64 = (nz == 0) ? 1 : 0;
}

// ---------------- CSR build ----------------
__global__ void zero_deg_kernel(){
    int i = blockIdx.x*256 + threadIdx.x;
    if (i < NNODES) g_deg[i] = 0;
}

__global__ void count_kernel(const void* edge){
    int e = blockIdx.x*256 + threadIdx.x;
    if (e >= NEDGES) return;
    int d;
    if (g_is64) d = (int)((const long long*)edge)[NEDGES + e];
    else        d = ((const int*)edge)[NEDGES + e];
    atomicAdd(&g_deg[d], 1);
}

__global__ void scan_kernel(){
    __shared__ int sm[1024];
    int t = threadIdx.x;
    int loc[8]; int s = 0;
#pragma unroll
    for (int j = 0; j < 8; j++){ loc[j] = s; s += g_deg[t*8 + j]; }
    sm[t] = s; __syncthreads();
    for (int off = 1; off < 1024; off <<= 1){
        int v = (t >= off) ? sm[t-off] : 0;
        __syncthreads();
        sm[t] += v;
        __syncthreads();
    }
    int base = (t == 0) ? 0 : sm[t-1];
#pragma unroll
    for (int j = 0; j < 8; j++){
        int r = base + loc[j];
        g_rowptr[t*8 + j] = r;
        g_cursor[t*8 + j] = r;
    }
    if (t == 1023) g_rowptr[NNODES] = sm[1023];
}

__global__ void scatter_kernel(const void* edge){
    int e = blockIdx.x*256 + threadIdx.x;
    if (e >= NEDGES) return;
    int s, d;
    if (g_is64){
        s = (int)((const long long*)edge)[e];
        d = (int)((const long long*)edge)[NEDGES + e];
    } else {
        s = ((const int*)edge)[e];
        d = ((const int*)edge)[NEDGES + e];
    }
    int pos = atomicAdd(&g_cursor[d], 1);
    g_srcs[pos] = s;
}

// ---------------- layer 1 linear + attention logits ----------------
__global__ __launch_bounds__(64) void lin1_kernel(const float* __restrict__ x,
                                                  const float* __restrict__ W1,
                                                  const float* __restrict__ a_s,
                                                  const float* __restrict__ a_d){
    __shared__ float xs[16];
    __shared__ float Ws[16*64];
    int n = blockIdx.x, t = threadIdx.x;
    if (t < 16) xs[t] = x[n*16 + t];
    for (int i = t; i < 16*64; i += 64) Ws[i] = W1[i];
    __syncthreads();
    float acc = 0.f;
#pragma unroll
    for (int k = 0; k < 16; k++) acc += xs[k] * Ws[k*64 + t];
    g_h1lin[n*64 + t] = acc;
    int c = t & 7;
    float ps = acc * a_s[t];
    float pd = acc * a_d[t];
#pragma unroll
    for (int off = 4; off; off >>= 1){
        ps += __shfl_down_sync(0xffffffffu, ps, off);
        pd += __shfl_down_sync(0xffffffffu, pd, off);
    }
    if (c == 0){ g_as1[n*8 + (t>>3)] = ps; g_ad1[n*8 + (t>>3)] = pd; }
}

// ---------------- GAT aggregation (dst-centric, segment softmax) ----------------
__global__ __launch_bounds__(64) void agg1_kernel(const float* __restrict__ bias){
    int d = blockIdx.x, t = threadIdx.x;
    __shared__ float adl[8], m[8], den[8];
    if (t < 8) adl[t] = g_ad1[d*8 + t];
    __syncthreads();
    int beg = g_rowptr[d], end = g_rowptr[d+1];
    if (t < 8){
        float mm = lrelu(g_as1[d*8 + t] + adl[t]);   // self loop
        for (int i = beg; i < end; i++){
            int s = g_srcs[i];
            mm = fmaxf(mm, lrelu(g_as1[s*8 + t] + adl[t]));
        }
        m[t] = mm;
    }
    __syncthreads();
    int hd = t >> 3; bool rep = (t & 7) == 0;
    float mh = m[hd], ad = adl[hd];
    float acc = 0.f, dsum = 0.f;
    {   // self loop
        float w = __expf(lrelu(g_as1[d*8 + hd] + ad) - mh);
        if (rep) dsum += w;
        acc += w * g_h1lin[d*64 + t];
    }
    for (int i = beg; i < end; i++){
        int s = g_srcs[i];
        float w = __expf(lrelu(g_as1[s*8 + hd] + ad) - mh);
        if (rep) dsum += w;
        acc += w * g_h1lin[s*64 + t];
    }
    if (rep) den[hd] = dsum + 1e-16f;
    __syncthreads();
    g_h1[d*64 + t] = fmaxf(acc / den[hd] + bias[t], 0.f);
}

__global__ __launch_bounds__(256) void agg2_kernel(const float* __restrict__ bias){
    int d = blockIdx.x, t = threadIdx.x;
    __shared__ float adl[8], m[8], den[8];
    if (t < 8) adl[t] = g_ad2[d*8 + t];
    __syncthreads();
    int beg = g_rowptr[d], end = g_rowptr[d+1];
    if (t < 8){
        float mm = lrelu(g_as2[d*8 + t] + adl[t]);
        for (int i = beg; i < end; i++){
            int s = g_srcs[i];
            mm = fmaxf(mm, lrelu(g_as2[s*8 + t] + adl[t]));
        }
        m[t] = mm;
    }
    __syncthreads();
    int hd = t >> 5; bool rep = (t & 31) == 0;
    float mh = m[hd], ad = adl[hd];
    float4 acc = {0.f,0.f,0.f,0.f}; float dsum = 0.f;
    {   // self loop
        float w = __expf(lrelu(g_as2[d*8 + hd] + ad) - mh);
        if (rep) dsum += w;
        float4 v = *(const float4*)(g_h2lin + (size_t)d*1024 + t*4);
        acc.x += w*v.x; acc.y += w*v.y; acc.z += w*v.z; acc.w += w*v.w;
    }
    for (int i = beg; i < end; i++){
        int s = g_srcs[i];
        float w = __expf(lrelu(g_as2[s*8 + hd] + ad) - mh);
        if (rep) dsum += w;
        float4 v = *(const float4*)(g_h2lin + (size_t)s*1024 + t*4);
        acc.x += w*v.x; acc.y += w*v.y; acc.z += w*v.z; acc.w += w*v.w;
    }
    if (rep) den[hd] = dsum + 1e-16f;
    __syncthreads();
    float inv = 1.f / den[hd];
    float4 b4 = *(const float4*)(bias + t*4);
    float4 o;
    o.x = fmaxf(acc.x*inv + b4.x, 0.f);
    o.y = fmaxf(acc.y*inv + b4.y, 0.f);
    o.z = fmaxf(acc.z*inv + b4.z, 0.f);
    o.w = fmaxf(acc.w*inv + b4.w, 0.f);
    *(float4*)(g_h2 + (size_t)d*1024 + t*4) = o;
}

// ---------------- layer 2 GEMM: h1[8192,64] @ W2[64,1024] ----------------
__global__ __launch_bounds__(256) void gemm2_kernel(const float* __restrict__ W2){
    __shared__ float As[64][68];
    __shared__ float Bs[64][68];
    int t = threadIdx.x;
    int n0 = blockIdx.x*64, m0 = blockIdx.y*64;
#pragma unroll
    for (int q = 0; q < 4; q++){
        int fid = q*256 + t;
        int row = fid >> 4, c4 = fid & 15;
        *(float4*)(&As[row][c4*4]) = *(const float4*)(g_h1 + (m0+row)*64 + c4*4);
        *(float4*)(&Bs[row][c4*4]) = *(const float4*)(W2 + row*1024 + n0 + c4*4);
    }
    __syncthreads();
    int tx = t & 15, ty = t >> 4;
    float acc[4][4] = {};
#pragma unroll
    for (int k = 0; k < 64; k++){
        float a[4], b[4];
#pragma unroll
        for (int i = 0; i < 4; i++) a[i] = As[ty*4 + i][k];
#pragma unroll
        for (int j = 0; j < 4; j++) b[j] = Bs[k][tx*4 + j];
#pragma unroll
        for (int i = 0; i < 4; i++)
#pragma unroll
            for (int j = 0; j < 4; j++) acc[i][j] += a[i]*b[j];
    }
#pragma unroll
    for (int i = 0; i < 4; i++){
        float4 o = {acc[i][0], acc[i][1], acc[i][2], acc[i][3]};
        *(float4*)(g_h2lin + (size_t)(m0 + ty*4 + i)*1024 + n0 + tx*4) = o;
    }
}

// ---------------- layer 2 attention logits ----------------
__global__ __launch_bounds__(256) void alpha2_kernel(const float* __restrict__ a_s,
                                                     const float* __restrict__ a_d){
    int n = blockIdx.x;
    int w = threadIdx.x >> 5, l = threadIdx.x & 31;
    float4 v  = *(const float4*)(g_h2lin + (size_t)n*1024 + w*128 + l*4);
    float4 s4 = *(const float4*)(a_s + w*128 + l*4);
    float4 d4 = *(const float4*)(a_d + w*128 + l*4);
    float ps = v.x*s4.x + v.y*s4.y + v.z*s4.z + v.w*s4.w;
    float pd = v.x*d4.x + v.y*d4.y + v.z*d4.z + v.w*d4.w;
#pragma unroll
    for (int off = 16; off; off >>= 1){
        ps += __shfl_down_sync(0xffffffffu, ps, off);
        pd += __shfl_down_sync(0xffffffffu, pd, off);
    }
    if (l == 0){ g_as2[n*8 + w] = ps; g_ad2[n*8 + w] = pd; }
}

// ---------------- adv head partial GEMV: h2flat[8,1M] @ adv_w[1M,16] ----------------
#define ADV_KSPAN 2048
#define ADV_KT    256
__global__ __launch_bounds__(256) void adv_kernel(const float* __restrict__ W){
    __shared__ float Ws[ADV_KT*16];
    __shared__ float Hs[8*ADV_KT];
    int t = threadIdx.x;
    int p = t & 127, kh = t >> 7;
    int b = p >> 4, col = p & 15;
    float acc = 0.f;
    int kbase = blockIdx.x * ADV_KSPAN;
    for (int tile = 0; tile < ADV_KSPAN/ADV_KT; tile++){
        int k0 = kbase + tile*ADV_KT;
        __syncthreads();
#pragma unroll
        for (int q = 0; q < 4; q++){
            int fid = q*256 + t;
            ((float4*)Ws)[fid] = ((const float4*)(W + (size_t)k0*16))[fid];
        }
#pragma unroll
        for (int q = 0; q < 2; q++){
            int fid = q*256 + t; int bb = fid >> 6, c4 = fid & 63;
            ((float4*)(Hs + bb*ADV_KT))[c4] =
                *(const float4*)(g_h2 + (size_t)bb*1048576 + k0 + c4*4);
        }
        __syncthreads();
        const float* hrow = Hs + b*ADV_KT + kh*128;
        const float* wrow = Ws + kh*128*16 + col;
#pragma unroll 8
        for (int kk = 0; kk < 128; kk++) acc += hrow[kk] * wrow[kk*16];
    }
    __shared__ float red[256];
    red[t] = acc; __syncthreads();
    if (kh == 0) g_advp[blockIdx.x*128 + p] = acc + red[t + 128];
}

// ---------------- val1 head partial GEMV: h2flat[8,1M] @ val1_w[1M,64] ----------------
#define VAL_KSPAN 2048
#define VAL_KT    128
__global__ __launch_bounds__(256) void val_kernel(const float* __restrict__ W){
    __shared__ float Ws[VAL_KT*64];
    __shared__ float Hs[8*VAL_KT];
    int t = threadIdx.x;
    int p = t & 127, kh = t >> 7;
    int b = p >> 4, c4 = p & 15;
    float4 acc = {0.f,0.f,0.f,0.f};
    int kbase = blockIdx.x * VAL_KSPAN;
    for (int tile = 0; tile < VAL_KSPAN/VAL_KT; tile++){
        int k0 = kbase + tile*VAL_KT;
        __syncthreads();
#pragma unroll
        for (int q = 0; q < 8; q++){
            int fid = q*256 + t;
            ((float4*)Ws)[fid] = ((const float4*)(W + (size_t)k0*64))[fid];
        }
        {
            int fid = t; int bb = fid >> 5, cc = fid & 31;
            ((float4*)(Hs + bb*VAL_KT))[cc] =
                *(const float4*)(g_h2 + (size_t)bb*1048576 + k0 + cc*4);
        }
        __syncthreads();
        const float*  hrow = Hs + b*VAL_KT + kh*64;
        const float4* wrow = (const float4*)Ws + kh*64*16 + c4;
#pragma unroll 4
        for (int kk = 0; kk < 64; kk++){
            float h = hrow[kk]; float4 w = wrow[kk*16];
            acc.x += h*w.x; acc.y += h*w.y; acc.z += h*w.z; acc.w += h*w.w;
        }
    }
    __shared__ float4 red[256];
    red[t] = acc; __syncthreads();
    if (kh == 0){
        float4 o = red[t + 128];
        acc.x += o.x; acc.y += o.y; acc.z += o.z; acc.w += o.w;
        ((float4*)g_valp)[blockIdx.x*128 + p] = acc;
    }
}

// ---------------- finalize: reduce partials, val MLP, dueling combine ----------------
__global__ __launch_bounds__(512) void final_kernel(const float* __restrict__ adv_b,
                                                    const float* __restrict__ v1b,
                                                    const float* __restrict__ v2w,
                                                    const float* __restrict__ v2b,
                                                    const float* __restrict__ v3w,
                                                    const float* __restrict__ v3b,
                                                    float* __restrict__ out){
    int t = threadIdx.x;
    __shared__ float v1[512], v2s[512], vS[8], advs[128];
    {
        float s = 0.f;
        for (int blk = 0; blk < 512; blk++) s += g_valp[blk*512 + t];
        v1[t] = fmaxf(s + v1b[t & 63], 0.f);
    }
    if (t < 128){
        float a = 0.f;
        for (int blk = 0; blk < 512; blk++) a += g_advp[blk*128 + t];
        advs[t] = fmaxf(a + adv_b[t & 15], 0.f);
    }
    __syncthreads();
    {
        int b = t >> 6, c = t & 63;
        float s2 = v2b[c];
        for (int k = 0; k < 64; k++) s2 += v1[b*64 + k] * v2w[k*64 + c];
        v2s[t] = fmaxf(s2, 0.f);
    }
    __syncthreads();
    if (t < 8){
        float s3 = v3b[0];
        for (int k = 0; k < 64; k++) s3 += v2s[t*64 + k] * v3w[k];
        vS[t] = s3;
    }
    __syncthreads();
    if (t < 128){
        int base = t & ~3;
        float mean = 0.25f*(advs[base] + advs[base+1] + advs[base+2] + advs[base+3]);
        out[t] = vS[t >> 4] + advs[t] - mean;
    }
}

// ---------------- launch ----------------
extern "C" void kernel_launch(void* const* d_in, const int* in_sizes, int n_in,
                              void* d_out, int out_size){
    const float* x      = (const float*)d_in[0];
    const void*  edge   = d_in[1];
    const float* W1     = (const float*)d_in[2];
    const float* a_src1 = (const float*)d_in[3];
    const float* a_dst1 = (const float*)d_in[4];
    const float* b1     = (const float*)d_in[5];
    const float* W2     = (const float*)d_in[6];
    const float* a_src2 = (const float*)d_in[7];
    const float* a_dst2 = (const float*)d_in[8];
    const float* b2     = (const float*)d_in[9];
    const float* adv_w  = (const float*)d_in[10];
    const float* adv_b  = (const float*)d_in[11];
    const float* val1_w = (const float*)d_in[12];
    const float* val1_b = (const float*)d_in[13];
    const float* val2_w = (const float*)d_in[14];
    const float* val2_b = (const float*)d_in[15];
    const float* val3_w = (const float*)d_in[16];
    const float* val3_b = (const float*)d_in[17];
    float* out = (float*)d_out;

    detect_kernel<<<1, 256>>>((const int*)edge);
    zero_deg_kernel<<<(NNODES+255)/256, 256>>>();
    count_kernel<<<(NEDGES+255)/256, 256>>>(edge);
    scan_kernel<<<1, 1024>>>();
    scatter_kernel<<<(NEDGES+255)/256, 256>>>(edge);

    lin1_kernel<<<NNODES, 64>>>(x, W1, a_src1, a_dst1);
    agg1_kernel<<<NNODES, 64>>>(b1);

    gemm2_kernel<<<dim3(16, 128), 256>>>(W2);
    alpha2_kernel<<<NNODES, 256>>>(a_src2, a_dst2);
    agg2_kernel<<<NNODES, 256>>>(b2);

    adv_kernel<<<512, 256>>>(adv_w);
    val_kernel<<<512, 256>>>(val1_w);
    final_kernel<<<1, 512>>>(adv_b, val1_b, val2_w, val2_b, val3_w, val3_b, out);
}

// round 2
// speedup vs baseline: 1.2332x; 1.2332x over previous
#include <cuda_runtime.h>
#include <cstddef>

#define HEADS  8
#define NNODES 8192
#define NEDGES 131072
#define NEG    0.2f

// ---------------- scratch (static __device__, no allocation) ----------------
__device__ float g_h1lin[NNODES*64];
__device__ float g_as1[NNODES*HEADS];
__device__ float g_ad1[NNODES*HEADS];
__device__ float g_h1[NNODES*64];
__device__ float g_h2lin[(size_t)NNODES*1024];   // 32MB
__device__ float g_as2[NNODES*HEADS];
__device__ float g_ad2[NNODES*HEADS];
__device__ float g_h2[(size_t)NNODES*1024];      // 32MB
__device__ int   g_deg[NNODES];
__device__ int   g_rowptr[NNODES+1];
__device__ int   g_cursor[NNODES];
__device__ int   g_srcs[NEDGES];
__device__ int   g_is64;
__device__ float g_Ms[64*8];
__device__ float g_Md[64*8];
__device__ float g_valacc[512];
__device__ float g_advacc[128];

__device__ __forceinline__ float lrelu(float x){ return x > 0.f ? x : NEG*x; }

// ---------------- prep: dtype sniff + zeroing + M = W2 @ a2 ----------------
__global__ __launch_bounds__(512) void prep_kernel(const int* __restrict__ e32,
                                                   const float* __restrict__ W2,
                                                   const float* __restrict__ a_s2,
                                                   const float* __restrict__ a_d2){
    int t = threadIdx.x;
    if (blockIdx.x == 0){
        __shared__ int nz;
        if (t == 0) nz = 0;
        __syncthreads();
        int v = 0;
        for (int i = t; i < 8192; i += 512) v |= e32[2*i+1];
        if (v) atomicOr(&nz, 1);
        for (int i = t; i < NNODES; i += 512) g_deg[i] = 0;
        g_valacc[t] = 0.f;
        if (t < 128) g_advacc[t] = 0.f;
        __syncthreads();
        if (t == 0) g_is64 = (nz == 0) ? 1 : 0;
    } else {
        int k = blockIdx.x - 1;   // 0..63
        __shared__ float sm[16][4];
        float w1  = W2[k*1024 + t];
        float w2v = W2[k*1024 + 512 + t];
        float p1s = w1  * a_s2[t];
        float p1d = w1  * a_d2[t];
        float p2s = w2v * a_s2[512 + t];
        float p2d = w2v * a_d2[512 + t];
#pragma unroll
        for (int off = 16; off; off >>= 1){
            p1s += __shfl_down_sync(~0u, p1s, off);
            p1d += __shfl_down_sync(~0u, p1d, off);
            p2s += __shfl_down_sync(~0u, p2s, off);
            p2d += __shfl_down_sync(~0u, p2d, off);
        }
        int w = t >> 5, l = t & 31;
        if (l == 0){ sm[w][0]=p1s; sm[w][1]=p1d; sm[w][2]=p2s; sm[w][3]=p2d; }
        __syncthreads();
        if (t < 8){
            float ms, md;
            if (t < 4){
                int b = t*4;
                ms = sm[b][0]+sm[b+1][0]+sm[b+2][0]+sm[b+3][0];
                md = sm[b][1]+sm[b+1][1]+sm[b+2][1]+sm[b+3][1];
            } else {
                int b = (t-4)*4;
                ms = sm[b][2]+sm[b+1][2]+sm[b+2][2]+sm[b+3][2];
                md = sm[b][3]+sm[b+1][3]+sm[b+2][3]+sm[b+3][3];
            }
            g_Ms[k*8 + t] = ms;
            g_Md[k*8 + t] = md;
        }
    }
}

// ---------------- CSR build ----------------
__global__ void count_kernel(const void* edge){
    int e = blockIdx.x*256 + threadIdx.x;
    if (e >= NEDGES) return;
    int d;
    if (g_is64) d = (int)((const long long*)edge)[NEDGES + e];
    else        d = ((const int*)edge)[NEDGES + e];
    atomicAdd(&g_deg[d], 1);
}

__global__ __launch_bounds__(1024) void scan_kernel(){
    int t = threadIdx.x, lane = t & 31, w = t >> 5;
    int loc[8]; int s = 0;
#pragma unroll
    for (int j = 0; j < 8; j++){ loc[j] = s; s += g_deg[t*8 + j]; }
    int v = s;
#pragma unroll
    for (int off = 1; off < 32; off <<= 1){
        int n = __shfl_up_sync(~0u, v, off);
        if (lane >= off) v += n;
    }
    __shared__ int wsum[32];
    if (lane == 31) wsum[w] = v;
    __syncthreads();
    if (t < 32){
        int x2 = wsum[t];
#pragma unroll
        for (int off = 1; off < 32; off <<= 1){
            int n = __shfl_up_sync(~0u, x2, off);
            if (t >= off) x2 += n;
        }
        wsum[t] = x2;
    }
    __syncthreads();
    int base = v - s + (w ? wsum[w-1] : 0);
#pragma unroll
    for (int j = 0; j < 8; j++){
        int r = base + loc[j];
        g_rowptr[t*8 + j] = r;
        g_cursor[t*8 + j] = r;
    }
    if (t == 1023) g_rowptr[NNODES] = wsum[31];
}

__global__ void scatter_kernel(const void* edge){
    int e = blockIdx.x*256 + threadIdx.x;
    if (e >= NEDGES) return;
    int s, d;
    if (g_is64){
        s = (int)((const long long*)edge)[e];
        d = (int)((const long long*)edge)[NEDGES + e];
    } else {
        s = ((const int*)edge)[e];
        d = ((const int*)edge)[NEDGES + e];
    }
    int pos = atomicAdd(&g_cursor[d], 1);
    g_srcs[pos] = s;
}

// ---------------- layer 1 linear + attention logits (4 nodes / block) ------
__global__ __launch_bounds__(256) void lin1_kernel(const float* __restrict__ x,
                                                   const float* __restrict__ W1,
                                                   const float* __restrict__ a_s,
                                                   const float* __restrict__ a_d){
    __shared__ float Ws[16*64];
    __shared__ float xs[4][16];
    int t = threadIdx.x;
    int nl = t >> 6, tc = t & 63;
    int n = blockIdx.x*4 + nl;
    for (int i = t; i < 1024; i += 256) Ws[i] = W1[i];
    if (t < 64) xs[t >> 4][t & 15] = x[blockIdx.x*64 + t];
    __syncthreads();
    float acc = 0.f;
#pragma unroll
    for (int k = 0; k < 16; k++) acc += xs[nl][k] * Ws[k*64 + tc];
    g_h1lin[n*64 + tc] = acc;
    float ps = acc * a_s[tc];
    float pd = acc * a_d[tc];
#pragma unroll
    for (int off = 4; off; off >>= 1){
        ps += __shfl_down_sync(~0u, ps, off);
        pd += __shfl_down_sync(~0u, pd, off);
    }
    if ((tc & 7) == 0){
        g_as1[n*8 + (tc>>3)] = ps;
        g_ad1[n*8 + (tc>>3)] = pd;
    }
}

// ---------------- GAT1 aggregation + alpha2 epilogue ----------------
__global__ __launch_bounds__(64) void agg1_kernel(const float* __restrict__ bias){
    int d = blockIdx.x, t = threadIdx.x;
    int g = t >> 3, l8 = t & 7, l32 = t & 31, wid = t >> 5;
    __shared__ float adl[8], m[8], wself[8], den_s[8];
    __shared__ float ws[64*8];
    __shared__ int   sidx[64];
    __shared__ float prS[2][8], prD[2][8];
    if (t < 8) adl[t] = g_ad1[d*8 + t];
    __syncthreads();
    int beg = g_rowptr[d], end = g_rowptr[d+1], deg = end - beg;
    float ad = adl[g];
    float sv = lrelu(g_as1[d*8 + g] + ad);
    float mm = sv;
    for (int i = beg + l8; i < end; i += 8)
        mm = fmaxf(mm, lrelu(g_as1[g_srcs[i]*8 + g] + ad));
    mm = fmaxf(mm, __shfl_down_sync(~0u, mm, 4));
    mm = fmaxf(mm, __shfl_down_sync(~0u, mm, 2));
    mm = fmaxf(mm, __shfl_down_sync(~0u, mm, 1));
    if (l8 == 0){ m[g] = mm; wself[g] = __expf(sv - mm); }
    __syncthreads();
    float acc = wself[g] * g_h1lin[d*64 + t];
    float dp = 0.f;
    for (int c0 = 0; c0 < deg; c0 += 64){
        int cn = min(64, deg - c0);
        __syncthreads();
        if (t < cn) sidx[t] = g_srcs[beg + c0 + t];
        __syncthreads();
        for (int idx = t; idx < cn*8; idx += 64){
            int e = idx >> 3, h = idx & 7;
            ws[idx] = __expf(lrelu(g_as1[sidx[e]*8 + h] + adl[h]) - m[h]);
        }
        __syncthreads();
        for (int e = l8; e < cn; e += 8) dp += ws[e*8 + g];
        int e = 0;
        for (; e + 4 <= cn; e += 4){
            int s0 = sidx[e], s1 = sidx[e+1], s2 = sidx[e+2], s3 = sidx[e+3];
            float w0 = ws[e*8+g], w1 = ws[(e+1)*8+g], w2 = ws[(e+2)*8+g], w3 = ws[(e+3)*8+g];
            float v0 = g_h1lin[s0*64 + t];
            float v1 = g_h1lin[s1*64 + t];
            float v2 = g_h1lin[s2*64 + t];
            float v3 = g_h1lin[s3*64 + t];
            acc += w0*v0; acc += w1*v1; acc += w2*v2; acc += w3*v3;
        }
        for (; e < cn; e++) acc += ws[e*8+g] * g_h1lin[sidx[e]*64 + t];
    }
    dp += __shfl_down_sync(~0u, dp, 4);
    dp += __shfl_down_sync(~0u, dp, 2);
    dp += __shfl_down_sync(~0u, dp, 1);
    if (l8 == 0) den_s[g] = dp + wself[g] + 1e-16f;
    __syncthreads();
    float h1v = fmaxf(acc / den_s[g] + bias[t], 0.f);
    g_h1[d*64 + t] = h1v;
    // fused alpha2: as2[d,h] = h1[d,:] . Ms[:,h]
#pragma unroll
    for (int h = 0; h < 8; h++){
        float vs = h1v * g_Ms[t*8 + h];
        float vd = h1v * g_Md[t*8 + h];
#pragma unroll
        for (int off = 16; off; off >>= 1){
            vs += __shfl_down_sync(~0u, vs, off);
            vd += __shfl_down_sync(~0u, vd, off);
        }
        if (l32 == 0){ prS[wid][h] = vs; prD[wid][h] = vd; }
    }
    __syncthreads();
    if (t < 8){
        g_as2[d*8 + t] = prS[0][t] + prS[1][t];
        g_ad2[d*8 + t] = prD[0][t] + prD[1][t];
    }
}

// ---------------- layer 2 GEMM: h1[8192,64] @ W2[64,1024] ----------------
__global__ __launch_bounds__(256) void gemm2_kernel(const float* __restrict__ W2){
    __shared__ float As[64][68];
    __shared__ float Bs[64][68];
    int t = threadIdx.x;
    int n0 = blockIdx.x*64, m0 = blockIdx.y*64;
#pragma unroll
    for (int q = 0; q < 4; q++){
        int fid = q*256 + t;
        int row = fid >> 4, c4 = fid & 15;
        *(float4*)(&As[row][c4*4]) = *(const float4*)(g_h1 + (m0+row)*64 + c4*4);
        *(float4*)(&Bs[row][c4*4]) = *(const float4*)(W2 + row*1024 + n0 + c4*4);
    }
    __syncthreads();
    int tx = t & 15, ty = t >> 4;
    float acc[4][4] = {};
#pragma unroll
    for (int k = 0; k < 64; k++){
        float a[4], b[4];
#pragma unroll
        for (int i = 0; i < 4; i++) a[i] = As[ty*4 + i][k];
#pragma unroll
        for (int j = 0; j < 4; j++) b[j] = Bs[k][tx*4 + j];
#pragma unroll
        for (int i = 0; i < 4; i++)
#pragma unroll
            for (int j = 0; j < 4; j++) acc[i][j] += a[i]*b[j];
    }
#pragma unroll
    for (int i = 0; i < 4; i++){
        float4 o = {acc[i][0], acc[i][1], acc[i][2], acc[i][3]};
        *(float4*)(g_h2lin + (size_t)(m0 + ty*4 + i)*1024 + n0 + tx*4) = o;
    }
}

// ---------------- GAT2 aggregation ----------------
__global__ __launch_bounds__(256) void agg2_kernel(const float* __restrict__ bias){
    int d = blockIdx.x, t = threadIdx.x;
    int w = t >> 5, l = t & 31;
    __shared__ float adl[8], m[8], wself[8], den_s[8];
    __shared__ float ws[64*8];
    __shared__ int   sidx[64];
    if (t < 8) adl[t] = g_ad2[d*8 + t];
    __syncthreads();
    int beg = g_rowptr[d], end = g_rowptr[d+1], deg = end - beg;
    float ad = adl[w];
    float sv = lrelu(g_as2[d*8 + w] + ad);
    float mm = sv;
    for (int i = beg + l; i < end; i += 32)
        mm = fmaxf(mm, lrelu(g_as2[g_srcs[i]*8 + w] + ad));
#pragma unroll
    for (int off = 16; off; off >>= 1)
        mm = fmaxf(mm, __shfl_down_sync(~0u, mm, off));
    if (l == 0){ m[w] = mm; wself[w] = __expf(sv - mm); }
    __syncthreads();
    float4 acc;
    {
        float s0 = wself[w];
        float4 v = *(const float4*)(g_h2lin + (size_t)d*1024 + t*4);
        acc.x = s0*v.x; acc.y = s0*v.y; acc.z = s0*v.z; acc.w = s0*v.w;
    }
    float dp = 0.f;
    for (int c0 = 0; c0 < deg; c0 += 64){
        int cn = min(64, deg - c0);
        __syncthreads();
        if (t < cn) sidx[t] = g_srcs[beg + c0 + t];
        __syncthreads();
        for (int idx = t; idx < cn*8; idx += 256){
            int e = idx >> 3, h = idx & 7;
            ws[idx] = __expf(lrelu(g_as2[sidx[e]*8 + h] + adl[h]) - m[h]);
        }
        __syncthreads();
        for (int e = l; e < cn; e += 32) dp += ws[e*8 + w];
        int e = 0;
        for (; e + 4 <= cn; e += 4){
            int s0 = sidx[e], s1 = sidx[e+1], s2 = sidx[e+2], s3 = sidx[e+3];
            float w0 = ws[e*8+w], w1 = ws[(e+1)*8+w], w2 = ws[(e+2)*8+w], w3 = ws[(e+3)*8+w];
            float4 v0 = *(const float4*)(g_h2lin + (size_t)s0*1024 + t*4);
            float4 v1 = *(const float4*)(g_h2lin + (size_t)s1*1024 + t*4);
            float4 v2 = *(const float4*)(g_h2lin + (size_t)s2*1024 + t*4);
            float4 v3 = *(const float4*)(g_h2lin + (size_t)s3*1024 + t*4);
            acc.x += w0*v0.x; acc.y += w0*v0.y; acc.z += w0*v0.z; acc.w += w0*v0.w;
            acc.x += w1*v1.x; acc.y += w1*v1.y; acc.z += w1*v1.z; acc.w += w1*v1.w;
            acc.x += w2*v2.x; acc.y += w2*v2.y; acc.z += w2*v2.z; acc.w += w2*v2.w;
            acc.x += w3*v3.x; acc.y += w3*v3.y; acc.z += w3*v3.z; acc.w += w3*v3.w;
        }
        for (; e < cn; e++){
            float we = ws[e*8+w];
            float4 v = *(const float4*)(g_h2lin + (size_t)sidx[e]*1024 + t*4);
            acc.x += we*v.x; acc.y += we*v.y; acc.z += we*v.z; acc.w += we*v.w;
        }
    }
#pragma unroll
    for (int off = 16; off; off >>= 1) dp += __shfl_down_sync(~0u, dp, off);
    if (l == 0) den_s[w] = dp + wself[w] + 1e-16f;
    __syncthreads();
    float inv = 1.f / den_s[w];
    float4 b4 = *(const float4*)(bias + t*4);
    float4 o;
    o.x = fmaxf(acc.x*inv + b4.x, 0.f);
    o.y = fmaxf(acc.y*inv + b4.y, 0.f);
    o.z = fmaxf(acc.z*inv + b4.z, 0.f);
    o.w = fmaxf(acc.w*inv + b4.w, 0.f);
    *(float4*)(g_h2 + (size_t)d*1024 + t*4) = o;
}

// ---------------- adv head: h2flat[8,1M] @ adv_w[1M,16] ----------------
#define ADV_SPAN 2048
#define ADV_SUB  512
__global__ __launch_bounds__(256) void adv_kernel(const float* __restrict__ W){
    __shared__ __align__(16) float sbuf[8192];   // 32KB: Hs[8][512] then red[256][8] float4
    float* Hs = sbuf;
    int t = threadIdx.x;
    int c4 = t & 3, j = t >> 2;           // j in 0..63
    int kbase = blockIdx.x * ADV_SPAN;
    const float4* W4 = (const float4*)W;
    float4 acc[8];
#pragma unroll
    for (int b = 0; b < 8; b++) acc[b] = make_float4(0.f,0.f,0.f,0.f);
    for (int st = 0; st < ADV_SPAN/ADV_SUB; st++){
        int k0 = kbase + st*ADV_SUB;
        __syncthreads();
#pragma unroll
        for (int q = 0; q < 4; q++){
            int idx = q*256 + t;
            int b = idx >> 7, cc = idx & 127;
            *(float4*)(Hs + b*ADV_SUB + cc*4) =
                *(const float4*)(g_h2 + (size_t)b*1048576 + k0 + cc*4);
        }
        __syncthreads();
#pragma unroll 2
        for (int i = 0; i < ADV_SUB/64; i++){
            int k = j + 64*i;
            float4 w4 = W4[(size_t)(k0 + k)*4 + c4];
#pragma unroll
            for (int b = 0; b < 8; b++){
                float h = Hs[b*ADV_SUB + k];
                acc[b].x += h*w4.x; acc[b].y += h*w4.y;
                acc[b].z += h*w4.z; acc[b].w += h*w4.w;
            }
        }
    }
    __syncthreads();
    float4* red = (float4*)sbuf;          // [256][8]
#pragma unroll
    for (int b = 0; b < 8; b++) red[t*8 + b] = acc[b];
    __syncthreads();
    if (t < 32){
        int b = t >> 2, cc = t & 3;
        float4 s = make_float4(0.f,0.f,0.f,0.f);
#pragma unroll
        for (int jj = 0; jj < 64; jj++){
            float4 v = red[(jj*4 + cc)*8 + b];
            s.x += v.x; s.y += v.y; s.z += v.z; s.w += v.w;
        }
        float* dst = g_advacc + b*16 + cc*4;
        atomicAdd(dst+0, s.x); atomicAdd(dst+1, s.y);
        atomicAdd(dst+2, s.z); atomicAdd(dst+3, s.w);
    }
}

// ---------------- val1 head: h2flat[8,1M] @ val1_w[1M,64] ----------------
#define VAL_SPAN 2048
#define VAL_SUB  512
__global__ __launch_bounds__(256) void val_kernel(const float* __restrict__ W){
    __shared__ __align__(16) float sbuf[8192];
    float* Hs = sbuf;
    int t = threadIdx.x;
    int c4 = t & 15, j = t >> 4;          // j in 0..15
    int kbase = blockIdx.x * VAL_SPAN;
    const float4* W4 = (const float4*)W;
    float4 acc[8];
#pragma unroll
    for (int b = 0; b < 8; b++) acc[b] = make_float4(0.f,0.f,0.f,0.f);
    for (int st = 0; st < VAL_SPAN/VAL_SUB; st++){
        int k0 = kbase + st*VAL_SUB;
        __syncthreads();
#pragma unroll
        for (int q = 0; q < 4; q++){
            int idx = q*256 + t;
            int b = idx >> 7, cc = idx & 127;
            *(float4*)(Hs + b*VAL_SUB + cc*4) =
                *(const float4*)(g_h2 + (size_t)b*1048576 + k0 + cc*4);
        }
        __syncthreads();
#pragma unroll 4
        for (int i = 0; i < VAL_SUB/16; i++){
            int k = j + 16*i;
            float4 w4 = W4[(size_t)(k0 + k)*16 + c4];
#pragma unroll
            for (int b = 0; b < 8; b++){
                float h = Hs[b*VAL_SUB + k];
                acc[b].x += h*w4.x; acc[b].y += h*w4.y;
                acc[b].z += h*w4.z; acc[b].w += h*w4.w;
            }
        }
    }
    __syncthreads();
    float4* red = (float4*)sbuf;          // [256][8]
#pragma unroll
    for (int b = 0; b < 8; b++) red[t*8 + b] = acc[b];
    __syncthreads();
    if (t < 128){
        int b = t >> 4, cc = t & 15;
        float4 s = make_float4(0.f,0.f,0.f,0.f);
#pragma unroll
        for (int jj = 0; jj < 16; jj++){
            float4 v = red[(jj*16 + cc)*8 + b];
            s.x += v.x; s.y += v.y; s.z += v.z; s.w += v.w;
        }
        float* dst = g_valacc + b*64 + cc*4;
        atomicAdd(dst+0, s.x); atomicAdd(dst+1, s.y);
        atomicAdd(dst+2, s.z); atomicAdd(dst+3, s.w);
    }
}

// ---------------- finalize: val MLP + dueling combine ----------------
__global__ __launch_bounds__(512) void final_kernel(const float* __restrict__ adv_b,
                                                    const float* __restrict__ v1b,
                                                    const float* __restrict__ v2w,
                                                    const float* __restrict__ v2b,
                                                    const float* __restrict__ v3w,
                                                    const float* __restrict__ v3b,
                                                    float* __restrict__ out){
    int t = threadIdx.x;
    __shared__ float v1[512], v2s[512], vS[8], advs[128];
    v1[t] = fmaxf(g_valacc[t] + v1b[t & 63], 0.f);
    if (t < 128) advs[t] = fmaxf(g_advacc[t] + adv_b[t & 15], 0.f);
    __syncthreads();
    {
        int b = t >> 6, c = t & 63;
        float s2 = v2b[c];
        for (int k = 0; k < 64; k++) s2 += v1[b*64 + k] * v2w[k*64 + c];
        v2s[t] = fmaxf(s2, 0.f);
    }
    __syncthreads();
    if (t < 8){
        float s3 = v3b[0];
        for (int k = 0; k < 64; k++) s3 += v2s[t*64 + k] * v3w[k];
        vS[t] = s3;
    }
    __syncthreads();
    if (t < 128){
        int base = t & ~3;
        float mean = 0.25f*(advs[base] + advs[base+1] + advs[base+2] + advs[base+3]);
        out[t] = vS[t >> 4] + advs[t] - mean;
    }
}

// ---------------- launch ----------------
extern "C" void kernel_launch(void* const* d_in, const int* in_sizes, int n_in,
                              void* d_out, int out_size){
    const float* x      = (const float*)d_in[0];
    const void*  edge   = d_in[1];
    const float* W1     = (const float*)d_in[2];
    const float* a_src1 = (const float*)d_in[3];
    const float* a_dst1 = (const float*)d_in[4];
    const float* b1     = (const float*)d_in[5];
    const float* W2     = (const float*)d_in[6];
    const float* a_src2 = (const float*)d_in[7];
    const float* a_dst2 = (const float*)d_in[8];
    const float* b2     = (const float*)d_in[9];
    const float* adv_w  = (const float*)d_in[10];
    const float* adv_b  = (const float*)d_in[11];
    const float* val1_w = (const float*)d_in[12];
    const float* val1_b = (const float*)d_in[13];
    const float* val2_w = (const float*)d_in[14];
    const float* val2_b = (const float*)d_in[15];
    const float* val3_w = (const float*)d_in[16];
    const float* val3_b = (const float*)d_in[17];
    float* out = (float*)d_out;

    prep_kernel<<<65, 512>>>((const int*)edge, W2, a_src2, a_dst2);
    count_kernel<<<NEDGES/256, 256>>>(edge);
    scan_kernel<<<1, 1024>>>();
    scatter_kernel<<<NEDGES/256, 256>>>(edge);

    lin1_kernel<<<NNODES/4, 256>>>(x, W1, a_src1, a_dst1);
    agg1_kernel<<<NNODES, 64>>>(b1);

    gemm2_kernel<<<dim3(16, 128), 256>>>(W2);
    agg2_kernel<<<NNODES, 256>>>(b2);

    adv_kernel<<<512, 256>>>(adv_w);
    val_kernel<<<512, 256>>>(val1_w);
    final_kernel<<<1, 512>>>(adv_b, val1_b, val2_w, val2_b, val3_w, val3_b, out);
}